// round 2
// baseline (speedup 1.0000x reference)
#include <cuda_runtime.h>
#include <cstdint>

#define BATCH 512
#define TLEN  512
#define S     64
#define NEG_INF -10000.0f

// Backpointer scratch: [b][t-1][n], uint8 (S=64 fits). 512*511*64 = 16,744,448 B.
__device__ __align__(16) unsigned char g_bptr[(size_t)BATCH * (TLEN - 1) * S];

// ---------------------------------------------------------------------------
// Forward Viterbi: one block per batch, 64 threads (thread = next-tag n).
// transitions row n lives in 64 registers; fv double-buffered in shared.
// ---------------------------------------------------------------------------
__global__ __launch_bounds__(S) void viterbi_fwd(
    const float* __restrict__ logits,      // (B, T, S)
    const float* __restrict__ masks,       // (B, T)
    const float* __restrict__ transitions, // (S, S) [next, prev]
    float* __restrict__ out)               // out[0..B): path_score
{
    const int b = blockIdx.x;
    const int n = threadIdx.x;

    __shared__ __align__(16) float fv[2][S];

    // Load my transitions row into registers (one-time, L2-served).
    float tr[S];
#pragma unroll
    for (int p = 0; p < S; p++) tr[p] = transitions[n * S + p];

    fv[0][n] = (n == 0) ? 0.0f : NEG_INF;
    __syncthreads();

    const float* lg = logits + (size_t)b * TLEN * S;
    const float* mk = masks + (size_t)b * TLEN;
    unsigned char* bp_out = g_bptr + (size_t)b * (TLEN - 1) * S;

    for (int t = 1; t < TLEN; t++) {
        // Prefetch emission early (hides LDG behind the reduction).
        float feat = lg[t * S + n];
        float m    = mk[t];

        const float4* fv4 = (const float4*)fv[(t - 1) & 1];

        // 4 blocked accumulators (p in [16j, 16j+16)), strict > keeps the
        // LOWEST p on ties within a block; merging j ascending with strict >
        // keeps the lowest block => exact jnp.argmax first-max semantics.
        float bv[4];
        int   bi[4];
#pragma unroll
        for (int j = 0; j < 4; j++) { bv[j] = -3.0e38f; bi[j] = 0; }

#pragma unroll
        for (int j = 0; j < 4; j++) {
#pragma unroll
            for (int q = 0; q < 4; q++) {
                float4 f = fv4[j * 4 + q];     // broadcast LDS.128
                int pb = j * 16 + q * 4;
                float c0 = f.x + tr[pb + 0];
                float c1 = f.y + tr[pb + 1];
                float c2 = f.z + tr[pb + 2];
                float c3 = f.w + tr[pb + 3];
                if (c0 > bv[j]) { bv[j] = c0; bi[j] = pb + 0; }
                if (c1 > bv[j]) { bv[j] = c1; bi[j] = pb + 1; }
                if (c2 > bv[j]) { bv[j] = c2; bi[j] = pb + 2; }
                if (c3 > bv[j]) { bv[j] = c3; bi[j] = pb + 3; }
            }
        }
        float best = bv[0]; int bidx = bi[0];
        if (bv[1] > best) { best = bv[1]; bidx = bi[1]; }
        if (bv[2] > best) { best = bv[2]; bidx = bi[2]; }
        if (bv[3] > best) { best = bv[3]; bidx = bi[3]; }

        bp_out[(t - 1) * S + n] = (unsigned char)bidx;

        // path_score = vmax (pre-feat) of LAST step at next == S-1 (torch quirk)
        if (t == TLEN - 1 && n == S - 1) out[b] = best;

        fv[t & 1][n] = best + feat * m;
        __syncthreads();
    }
}

// ---------------------------------------------------------------------------
// Backtrace: one block per batch. Stage the 32KB bptr table into shared,
// walk the serial chain in LDS, then coalesced float writes.
// ---------------------------------------------------------------------------
__global__ __launch_bounds__(64) void viterbi_back(float* __restrict__ out)
{
    const int b = blockIdx.x;
    __shared__ __align__(16) unsigned char sb[(TLEN - 1) * S]; // 32704 B
    __shared__ unsigned char seq[TLEN - 1];

    const uint4* src = (const uint4*)(g_bptr + (size_t)b * (TLEN - 1) * S);
    uint4* dst = (uint4*)sb;
    const int nvec = (TLEN - 1) * S / 16;  // 2044
    for (int i = threadIdx.x; i < nvec; i += 64) dst[i] = src[i];
    __syncthreads();

    if (threadIdx.x == 0) {
        // seed: bptrs[-1][:, S-1]; table re-applied once (torch quirk)
        int tag = sb[(TLEN - 2) * S + (S - 1)];
        for (int i = TLEN - 2; i >= 0; i--) {
            seq[i] = (unsigned char)tag;
            tag = sb[i * S + tag];
        }
    }
    __syncthreads();

    float* o = out + BATCH + (size_t)b * (TLEN - 1);
    for (int i = threadIdx.x; i < TLEN - 1; i += 64) o[i] = (float)seq[i];
}

extern "C" void kernel_launch(void* const* d_in, const int* in_sizes, int n_in,
                              void* d_out, int out_size)
{
    const float* logits      = (const float*)d_in[0];
    const float* masks       = (const float*)d_in[1];
    const float* transitions = (const float*)d_in[2];
    float* out = (float*)d_out;

    viterbi_fwd<<<BATCH, S>>>(logits, masks, transitions, out);
    viterbi_back<<<BATCH, 64>>>(out);
}

// round 4
// speedup vs baseline: 1.1444x; 1.1444x over previous
#include <cuda_runtime.h>
#include <cstdint>

#define BATCH 512
#define TLEN  512
#define S     64
#define NEG_INF -10000.0f
#define NTHR  128   // tid = 2*n + h ; n = next-tag, h = prev-half

// Packed f32x2 add (Blackwell): bitwise identical to two scalar FADD.rn.
__device__ __forceinline__ void fadd2(float& lo, float& hi,
                                      unsigned long long a, unsigned long long b) {
    unsigned long long s;
    asm("add.rn.f32x2 %0, %1, %2;" : "=l"(s) : "l"(a), "l"(b));
    unsigned int l, h;
    asm("mov.b64 {%0,%1}, %2;" : "=r"(l), "=r"(h) : "l"(s));
    lo = __uint_as_float(l);
    hi = __uint_as_float(h);
}

__device__ __forceinline__ void upd(float c, int p, float& bv, int& bi) {
    if (c > bv) { bv = c; bi = p; }   // strict >: lowest p wins ties
}

__global__ __launch_bounds__(NTHR) void viterbi_all(
    const float* __restrict__ logits,       // (B, T, S)
    const float* __restrict__ masks,        // (B, T)
    const float* __restrict__ transitions,  // (S, S) [next, prev]
    float* __restrict__ out)                // [0,B): path_score ; [B,...): best_seq
{
    const int b   = blockIdx.x;
    const int tid = threadIdx.x;
    const int n   = tid >> 1;      // next tag 0..63
    const int h   = tid & 1;       // prev half 0..1

    __shared__ __align__(16) float fvbuf[2][S];
    __shared__ __align__(16) float smask[TLEN];
    __shared__ __align__(16) unsigned char bp_s[(TLEN - 1) * S]; // 32704 B
    __shared__ __align__(16) unsigned char seq_s[TLEN];

    // ---- my 32 transitions as 16 packed f32x2 ----
    unsigned long long tr2[16];
    {
        const ulonglong2* tp =
            (const ulonglong2*)(transitions + n * S + h * 32);
#pragma unroll
        for (int i = 0; i < 8; i++) {
            ulonglong2 v = tp[i];
            tr2[2 * i]     = v.x;
            tr2[2 * i + 1] = v.y;
        }
    }

    // ---- stage mask row (2 KB) ----
    {
        const float4* ms = (const float4*)(masks + (size_t)b * TLEN);
        ((float4*)smask)[tid] = ms[tid];
    }

    // ---- init fv ----
    if (h == 0) fvbuf[0][n] = (n == 0) ? 0.0f : NEG_INF;
    __syncthreads();

    const float* lg = logits + (size_t)b * TLEN * S;

    // ---- depth-4 emission prefetch pipeline ----
    float fb[4];
#pragma unroll
    for (int i = 0; i < 4; i++) fb[i] = lg[(1 + i) * S + n];

#pragma unroll 4
    for (int t = 1; t < TLEN; t++) {
        float feat = fb[0];
        fb[0] = fb[1]; fb[1] = fb[2]; fb[2] = fb[3];
        int tp = t + 4; if (tp > TLEN - 1) tp = TLEN - 1;
        fb[3] = lg[tp * S + n];

        float m = smask[t];

        // load my 32 fv values (8 x LDS.128)
        const ulonglong2* fvp =
            (const ulonglong2*)(&fvbuf[(t - 1) & 1][32 * h]);
        ulonglong2 F[8];
#pragma unroll
        for (int i = 0; i < 8; i++) F[i] = fvp[i];

        // 4 accumulator chains, each over a contiguous ascending p-range
        float bv[4]; int bi[4];
#pragma unroll
        for (int j = 0; j < 4; j++) {
            bv[j] = -3.0e38f; bi[j] = 0;
#pragma unroll
            for (int u = 0; u < 2; u++) {
                ulonglong2 Fx = F[j * 2 + u];
                int k  = (j * 2 + u) * 2;        // packed-pair index
                int p0 = 32 * h + 2 * k;         // base prev index
                float c0, c1, c2, c3;
                fadd2(c0, c1, Fx.x, tr2[k]);
                upd(c0, p0 + 0, bv[j], bi[j]);
                upd(c1, p0 + 1, bv[j], bi[j]);
                fadd2(c2, c3, Fx.y, tr2[k + 1]);
                upd(c2, p0 + 2, bv[j], bi[j]);
                upd(c3, p0 + 3, bv[j], bi[j]);
            }
        }
        float v = bv[0]; int idx = bi[0];
        if (bv[1] > v) { v = bv[1]; idx = bi[1]; }
        if (bv[2] > v) { v = bv[2]; idx = bi[2]; }
        if (bv[3] > v) { v = bv[3]; idx = bi[3]; }

        // merge the two prev-halves: odd lane has the HIGHER p range,
        // strict > keeps the lower-p tie winner on even lanes.
        float ov = __shfl_xor_sync(0xffffffffu, v, 1);
        int   oi = __shfl_xor_sync(0xffffffffu, idx, 1);
        if (ov > v) { v = ov; idx = oi; }

        if (h == 0) {
            bp_s[(t - 1) * S + n] = (unsigned char)idx;
            // torch quirk: path_score = pre-feat vmax at n = S-1, last step
            if (t == TLEN - 1 && n == S - 1) out[b] = v;
            fvbuf[t & 1][n] = __fadd_rn(v, __fmul_rn(feat, m));
        }
        __syncthreads();
    }

    // ---- backtrace walk in shared (single thread, LDS chain) ----
    if (tid == 0) {
        int tag = bp_s[(TLEN - 2) * S + (S - 1)];   // seed (torch quirk)
        for (int i = TLEN - 2; i >= 0; i--) {
            seq_s[i] = (unsigned char)tag;
            tag = bp_s[i * S + tag];
        }
    }
    __syncthreads();

    // ---- coalesced output ----
    float* o = out + BATCH + (size_t)b * (TLEN - 1);
    for (int i = tid; i < TLEN - 1; i += NTHR) o[i] = (float)seq_s[i];
}

extern "C" void kernel_launch(void* const* d_in, const int* in_sizes, int n_in,
                              void* d_out, int out_size)
{
    const float* logits      = (const float*)d_in[0];
    const float* masks       = (const float*)d_in[1];
    const float* transitions = (const float*)d_in[2];
    float* out = (float*)d_out;

    viterbi_all<<<BATCH, NTHR>>>(logits, masks, transitions, out);
}